// round 15
// baseline (speedup 1.0000x reference)
#include <cuda_runtime.h>
#include <cstdint>

// Problem constants: features (B, D, L) f32, tois (B, N, 2) i32, MAX_SPAN=64
#define BB 16
#define DD 256
#define LL 4096
#define NQ 4096
#define CHUNKS 63            // c0 = start>>6 in [0,62] since start <= L-MAX_SPAN-1
#define SUBS 8               // n-subranges per batch (512 queries each)
#define SUBCAP 32            // per-sub-bin capacity; mean 8.1, ~8 sigma margin

// Plane geometry for the SoA smem scan buffer ics[4][32][33]:
// element (d, l) lives at plane l&3, row d, col l>>2. Col 32 is a zero pad.
#define PLANE 1056           // 32*33 floats per plane
#define ZOFF  32             // offset of the zero pad element (plane 0, col 32)
#define OFF(l) (((l) & 3) * PLANE + ((l) >> 2))

// Sub-binned scratch: every cell written by exactly one block per launch via
// plain stores -> no zeroing kernel needed, fully deterministic outputs.
__device__ int g_cnt8[BB * CHUNKS * SUBS];
__device__ int g_bins[BB * CHUNKS * SUBS * SUBCAP];

// ---------------------------------------------------------------------------
// Prepass: (b, n-subrange) blocks bin their 512 queries by start-chunk.
// Also writes the counts tail of the output (cumsum of per-batch N).
// ---------------------------------------------------------------------------
__global__ void __launch_bounds__(512) k_prep(const int* __restrict__ tois,
                                              float* __restrict__ out,
                                              int write_counts) {
    __shared__ int cur[CHUNKS];

    const int b   = blockIdx.x;
    const int sub = blockIdx.y;
    const int tid = threadIdx.x;

    if (tid < CHUNKS) cur[tid] = 0;
    __syncthreads();

    const int q = b * NQ + (sub << 9) + tid;
    const int c = tois[2 * q] >> 6;
    const int p = atomicAdd(&cur[c], 1);
    if (p < SUBCAP)
        g_bins[(((b * CHUNKS + c) << 3) + sub) * SUBCAP + p] = q;
    __syncthreads();

    if (tid < CHUNKS) {
        const int v = cur[tid];
        g_cnt8[((b * CHUNKS + tid) << 3) + sub] = v < SUBCAP ? v : SUBCAP;
    }

    if (write_counts && b == 0 && sub == 0 && tid < BB)
        out[(size_t)BB * NQ * 3 * DD + tid] = (float)((tid + 1) * NQ);
}

// ---------------------------------------------------------------------------
// Main fused kernel (PDL consumer). Block = (c0, 32-d slice h, b).
// Phase A (independent of prepass) runs first; then grid-dependency sync;
// then staging from bins; then phase B serves queries from smem.
// ---------------------------------------------------------------------------
__global__ void __launch_bounds__(256, 8) k_main(const float* __restrict__ feat,
                                                 const int* __restrict__ tois,
                                                 float* __restrict__ out) {
    __shared__ float ics[4 * PLANE];        // [plane][d(32)][col(33)]
    __shared__ int4  s_meta[SUBS * SUBCAP]; // byte offs packed, inv, q
    __shared__ int   s_cnt[SUBS];
    __shared__ int   s_total;

    const int c0 = blockIdx.x;        // 0..62
    const int h  = blockIdx.y;        // d slice 0..7 (32 d each)
    const int b  = blockIdx.z;
    const int tid  = threadIdx.x;
    const int w    = tid >> 5;
    const int lane = tid & 31;
    const int l0   = c0 << 6;

    // zero the pad column (col 32 of each plane/row): 128 elements
    if (tid < 128) ics[(tid >> 5) * PLANE + (tid & 31) * 33 + 32] = 0.0f;

    // ---- Phase A: 8 warps x 4 d-rows; lane owns a float4 of l (128 l).
    // width-16 shuffle scan restarts exactly at the 64-l chunk boundary.
    // SoA stores: plane k, [dd][lane] -> banks (dd+lane)%32, conflict-free.
    #pragma unroll
    for (int r = 0; r < 4; r++) {
        const int dd = (w << 2) + r;                   // local d row 0..31
        const int dg = (h << 5) + dd;                  // global d
        const float4 v = *reinterpret_cast<const float4*>(
            feat + ((size_t)b * DD + dg) * LL + l0 + 4 * lane);
        const float i0 = v.x;
        const float i1 = i0 + v.y;
        const float i2 = i1 + v.z;
        const float i3 = i2 + v.w;
        float s = i3;
        #pragma unroll
        for (int o = 1; o < 16; o <<= 1) {
            const float t = __shfl_up_sync(0xffffffffu, s, o, 16);
            if ((lane & 15) >= o) s += t;
        }
        const float pre = s - i3;                      // exclusive prefix in chunk
        const int rowb = dd * 33 + lane;
        ics[            rowb] = pre + i0;   // l = 4*lane+0
        ics[    PLANE + rowb] = pre + i1;   // l = 4*lane+1
        ics[2 * PLANE + rowb] = pre + i2;   // l = 4*lane+2
        ics[3 * PLANE + rowb] = pre + i3;   // l = 4*lane+3
    }

    // ---- Wait for k_prep's bins to be visible (PDL).
    cudaGridDependencySynchronize();

    const int bin8 = (b * CHUNKS + c0) << 3;
    if (tid < SUBS) s_cnt[tid] = g_cnt8[bin8 + tid];
    __syncthreads();                        // covers phase-A STS + s_cnt

    // ---- Stage: warp s compacts sub-bin s; lane computes full meta with
    // BYTE offsets (pre-shifted) so phase B has no shifts.
    // Packing: m.x = o_s[bits 0..13] | o_sm1<<16[bits 16..30] | fE<<31.
    // Extraction masks MUST NOT include bit 15 of the shifted halfword (fE).
    {
        int off = 0;
        #pragma unroll
        for (int k = 0; k < SUBS; k++) off += (k < w) ? s_cnt[k] : 0;
        const int cs = s_cnt[w];
        if (w == SUBS - 1 && lane == 0) s_total = off + cs;
        if (lane < cs) {
            const int q = g_bins[(bin8 + w) * SUBCAP + lane];
            const int2 t = __ldg(reinterpret_cast<const int2*>(tois) + q);
            const int sL = t.x - l0;          // [0,64)
            const int eL = t.y - 1 - l0;      // [0,127]
            const int o_s   = OFF(sL) << 2;
            const int o_sm1 = ((sL & 63) ? OFF(sL - 1) : ZOFF) << 2;
            const int o_e   = OFF(eL) << 2;
            const int o_em1 = ((eL & 63) ? OFF(eL - 1) : ZOFF) << 2;
            const int fE    = (eL >= 64) ? 1 : 0;
            int4 m;
            m.x = o_s | (o_sm1 << 16) | (fE << 31);
            m.y = o_e | (o_em1 << 16);
            m.z = __float_as_int(1.0f / (float)(t.y - t.x));
            m.w = q;
            s_meta[off + lane] = m;
        }
    }
    __syncthreads();

    // ---- Phase B: one query per warp per iteration; lane owns local d.
    // Next-iteration meta is prefetched into registers to break the
    // LDS.128 -> dependent-LDS serial chain.
    const char* smb = reinterpret_cast<const char*>(ics + lane * 33);
    const float E = *reinterpret_cast<const float*>(smb + ((3 * PLANE + 15) << 2));
    const int   hb = h << 5;
    const int   total = s_total;

    if (w < total) {
        int4 m = s_meta[w];
        for (int i = w; i < total; i += 8) {
            const int inext = i + 8;
            const int4 mn = (inext < total) ? s_meta[inext] : m;

            const int o_s   = m.x & 0x3FFC;           // bits 2..13
            const int o_sm1 = (m.x >> 16) & 0x7FFC;   // bits 2..14 — excludes fE@15
            const int o_e   = m.y & 0x3FFC;
            const int o_em1 = ((unsigned)m.y >> 16) & 0x7FFC;
            const float inv = __int_as_float(m.z);

            const float A  = *reinterpret_cast<const float*>(smb + o_s);
            const float Bv = *reinterpret_cast<const float*>(smb + o_sm1);
            const float C  = *reinterpret_cast<const float*>(smb + o_e);
            const float Dv = *reinterpret_cast<const float*>(smb + o_em1);

            const float Et   = (m.x < 0) ? E : 0.0f;
            const float head = A - Bv;
            const float tail = C - Dv;
            const float avg  = (C + Et - Bv) * inv;

            float* o = out + (size_t)m.w * (3 * DD) + hb + lane;
            o[0]      = head;
            o[DD]     = avg;
            o[2 * DD] = tail;

            m = mn;
        }
    }
}

extern "C" void kernel_launch(void* const* d_in, const int* in_sizes, int n_in,
                              void* d_out, int out_size) {
    const float* feat = (const float*)d_in[0];
    const int*   tois = (const int*)d_in[1];
    float*       out  = (float*)d_out;

    const long long total = (long long)BB * NQ * 3 * DD;  // 50,331,648
    const int write_counts = ((long long)out_size >= total + BB) ? 1 : 0;

    dim3 gp(BB, SUBS);                 // 128 blocks
    k_prep<<<gp, 512>>>(tois, out, write_counts);

    // k_main with programmatic stream serialization: it launches while k_prep
    // is still running; phase A overlaps the prepass, gridDepSync gates
    // the bin reads.
    dim3 g(CHUNKS, 8, BB);             // 63 x 8 x 16 = 8064 blocks
    cudaLaunchConfig_t cfg = {};
    cfg.gridDim  = g;
    cfg.blockDim = dim3(256, 1, 1);
    cudaLaunchAttribute attr[1];
    attr[0].id = cudaLaunchAttributeProgrammaticStreamSerialization;
    attr[0].val.programmaticStreamSerializationAllowed = 1;
    cfg.attrs = attr;
    cfg.numAttrs = 1;
    cudaLaunchKernelEx(&cfg, k_main, feat, tois, out);
}

// round 16
// speedup vs baseline: 1.3866x; 1.3866x over previous
#include <cuda_runtime.h>
#include <cstdint>

// Problem constants: features (B, D, L) f32, tois (B, N, 2) i32, MAX_SPAN=64
#define BB 16
#define DD 256
#define LL 4096
#define NQ 4096
#define CHUNKS 63            // c0 = start>>6 in [0,62] since start <= L-MAX_SPAN-1
#define SUBS 8               // n-subranges per batch (512 queries each)
#define SUBCAP 32            // per-sub-bin capacity; mean 8.1, ~8 sigma margin

// Plane geometry for the SoA smem scan buffer ics[4][32][33]:
// element (d, l) lives at plane l&3, row d, col l>>2. Col 32 is a zero pad.
#define PLANE 1056           // 32*33 floats per plane
#define ZOFF  32             // offset of the zero pad element (plane 0, col 32)
#define OFF(l) (((l) & 3) * PLANE + ((l) >> 2))

// Sub-binned scratch: every cell written by exactly one block per launch via
// plain stores -> no zeroing kernel needed, fully deterministic outputs.
__device__ int g_cnt8[BB * CHUNKS * SUBS];
__device__ int g_bins[BB * CHUNKS * SUBS * SUBCAP];

// ---------------------------------------------------------------------------
// Prepass: (b, n-subrange) blocks bin their 512 queries by start-chunk.
// Also writes the counts tail of the output (cumsum of per-batch N).
// ---------------------------------------------------------------------------
__global__ void __launch_bounds__(512) k_prep(const int* __restrict__ tois,
                                              float* __restrict__ out,
                                              int write_counts) {
    __shared__ int cur[CHUNKS];

    const int b   = blockIdx.x;
    const int sub = blockIdx.y;
    const int tid = threadIdx.x;

    if (tid < CHUNKS) cur[tid] = 0;
    __syncthreads();

    const int q = b * NQ + (sub << 9) + tid;
    const int c = tois[2 * q] >> 6;
    const int p = atomicAdd(&cur[c], 1);
    if (p < SUBCAP)
        g_bins[(((b * CHUNKS + c) << 3) + sub) * SUBCAP + p] = q;
    __syncthreads();

    if (tid < CHUNKS) {
        const int v = cur[tid];
        g_cnt8[((b * CHUNKS + tid) << 3) + sub] = v < SUBCAP ? v : SUBCAP;
    }

    if (write_counts && b == 0 && sub == 0 && tid < BB)
        out[(size_t)BB * NQ * 3 * DD + tid] = (float)((tid + 1) * NQ);
}

// ---------------------------------------------------------------------------
// Main fused kernel (PDL consumer). Block = (c0, 32-d slice h, b).
// Body is the R12 version (measured 49.3us) with ONLY the ordering changed:
// phase A first (independent of prepass), then gridDepSync, then staging,
// then R12's phase B verbatim.
// ---------------------------------------------------------------------------
__global__ void __launch_bounds__(256, 8) k_main(const float* __restrict__ feat,
                                                 const int* __restrict__ tois,
                                                 float* __restrict__ out) {
    __shared__ float ics[4 * PLANE];        // [plane][d(32)][col(33)]
    __shared__ int4  s_meta[SUBS * SUBCAP]; // {offs|offsm1<<16|fE<<31, offe|offem1<<16, inv, q}
    __shared__ int   s_cnt[SUBS];
    __shared__ int   s_total;

    const int c0 = blockIdx.x;        // 0..62
    const int h  = blockIdx.y;        // d slice 0..7 (32 d each)
    const int b  = blockIdx.z;
    const int tid  = threadIdx.x;
    const int w    = tid >> 5;
    const int lane = tid & 31;
    const int l0   = c0 << 6;

    // zero the pad column (col 32 of each plane/row): 128 elements
    if (tid < 128) ics[(tid >> 5) * PLANE + (tid & 31) * 33 + 32] = 0.0f;

    // ---- Phase A: 8 warps x 4 d-rows; lane owns a float4 of l (128 l).
    // width-16 shuffle scan restarts exactly at the 64-l chunk boundary.
    // SoA stores: plane k, [dd][lane] -> banks (dd+lane)%32, conflict-free.
    #pragma unroll
    for (int r = 0; r < 4; r++) {
        const int dd = (w << 2) + r;                   // local d row 0..31
        const int dg = (h << 5) + dd;                  // global d
        const float4 v = *reinterpret_cast<const float4*>(
            feat + ((size_t)b * DD + dg) * LL + l0 + 4 * lane);
        const float i0 = v.x;
        const float i1 = i0 + v.y;
        const float i2 = i1 + v.z;
        const float i3 = i2 + v.w;
        float s = i3;
        #pragma unroll
        for (int o = 1; o < 16; o <<= 1) {
            const float t = __shfl_up_sync(0xffffffffu, s, o, 16);
            if ((lane & 15) >= o) s += t;
        }
        const float pre = s - i3;                      // exclusive prefix in chunk
        const int rowb = dd * 33 + lane;
        ics[            rowb] = pre + i0;   // l = 4*lane+0
        ics[    PLANE + rowb] = pre + i1;   // l = 4*lane+1
        ics[2 * PLANE + rowb] = pre + i2;   // l = 4*lane+2
        ics[3 * PLANE + rowb] = pre + i3;   // l = 4*lane+3
    }

    // ---- Wait for k_prep's bins to be visible (PDL).
    cudaGridDependencySynchronize();

    const int bin8 = (b * CHUNKS + c0) << 3;
    if (tid < SUBS) s_cnt[tid] = g_cnt8[bin8 + tid];
    __syncthreads();

    // ---- Stage: warp s compacts sub-bin s; lane computes the full meta
    // (R12 packing: 15-bit float-index offsets, fE in bit 31 of m.x).
    {
        int off = 0;
        #pragma unroll
        for (int k = 0; k < SUBS; k++) off += (k < w) ? s_cnt[k] : 0;
        const int cs = s_cnt[w];
        if (w == SUBS - 1 && lane == 0) s_total = off + cs;
        if (lane < cs) {
            const int q = g_bins[(bin8 + w) * SUBCAP + lane];
            const int2 t = __ldg(reinterpret_cast<const int2*>(tois) + q);
            const int sL = t.x - l0;          // [0,64)
            const int eL = t.y - 1 - l0;      // [0,127]
            const int off_s   = OFF(sL);
            const int off_sm1 = (sL & 63) ? OFF(sL - 1) : ZOFF;
            const int off_e   = OFF(eL);
            const int off_em1 = (eL & 63) ? OFF(eL - 1) : ZOFF;
            const int fE      = (eL >= 64) ? 1 : 0;
            int4 m;
            m.x = off_s | (off_sm1 << 16) | (fE << 31);
            m.y = off_e | (off_em1 << 16);
            m.z = __float_as_int(1.0f / (float)(t.y - t.x));
            m.w = q;
            s_meta[off + lane] = m;
        }
    }
    __syncthreads();

    // ---- Phase B (R12 verbatim): one query per warp per iteration.
    const float* sm = ics + lane * 33;      // row base for this lane's d
    const float E = sm[3 * PLANE + 15];     // incl[63] (l=63: plane 3, col 15)
    const int   hb = h << 5;
    const int   total = s_total;

    for (int i = w; i < total; i += 8) {
        const int4 m = s_meta[i];                        // uniform LDS.128
        const int off_s   = m.x & 0x7FFF;
        const int off_sm1 = ((unsigned)m.x >> 16) & 0x7FFF;
        const int off_e   = m.y & 0xFFFF;
        const int off_em1 = (unsigned)m.y >> 16;
        const float inv   = __int_as_float(m.z);

        const float A  = sm[off_s];
        const float Bv = sm[off_sm1];
        const float C  = sm[off_e];
        const float Dv = sm[off_em1];

        const float Et   = (m.x < 0) ? E : 0.0f;
        const float head = A - Bv;
        const float tail = C - Dv;
        const float avg  = (C + Et - Bv) * inv;

        float* o = out + (size_t)m.w * (3 * DD) + hb + lane;
        o[0]      = head;
        o[DD]     = avg;
        o[2 * DD] = tail;
    }
}

extern "C" void kernel_launch(void* const* d_in, const int* in_sizes, int n_in,
                              void* d_out, int out_size) {
    const float* feat = (const float*)d_in[0];
    const int*   tois = (const int*)d_in[1];
    float*       out  = (float*)d_out;

    const long long total = (long long)BB * NQ * 3 * DD;  // 50,331,648
    const int write_counts = ((long long)out_size >= total + BB) ? 1 : 0;

    dim3 gp(BB, SUBS);                 // 128 blocks
    k_prep<<<gp, 512>>>(tois, out, write_counts);

    // PDL: k_main launches while k_prep runs; phase A overlaps the prepass,
    // gridDepSync gates the bin reads.
    dim3 g(CHUNKS, 8, BB);             // 63 x 8 x 16 = 8064 blocks
    cudaLaunchConfig_t cfg = {};
    cfg.gridDim  = g;
    cfg.blockDim = dim3(256, 1, 1);
    cudaLaunchAttribute attr[1];
    attr[0].id = cudaLaunchAttributeProgrammaticStreamSerialization;
    attr[0].val.programmaticStreamSerializationAllowed = 1;
    cfg.attrs = attr;
    cfg.numAttrs = 1;
    cudaLaunchKernelEx(&cfg, k_main, feat, tois, out);
}